// round 1
// baseline (speedup 1.0000x reference)
#include <cuda_runtime.h>

#define SEQ   600
#define BATCH 4096
#define INP   6
#define HID   30
#define OUTD  61
#define HP    32            // padded hidden units
#define ROWS  128           // 4 gates * HP
#define BBLK  32            // batch rows per block
#define NBLK  (BATCH / BBLK)  // 128 blocks
#define NTHR  256

typedef unsigned long long ull;

// ---------------- preprocessed weights (device globals, filled by prep kernel) ----------------
__device__ __align__(16) float2 g_Wd[ROWS][HID];   // W_hh dup-packed {w,w}, row = gate*HP + unit
__device__ __align__(16) float2 g_Wih[ROWS][INP];  // W_ih dup-packed
__device__ float g_bias[ROWS];                     // b_ih + b_hh (0 for padded units)
__device__ float g_M[HID][OUTD];                   // fused fc: M[j][o] = sum_k W1[k][j]*W2[o][k]
__device__ float g_bv[OUTD];                       // b2 + b1 @ W2^T

// ---------------- packed f32x2 helpers ----------------
__device__ __forceinline__ void ffma2(ull& acc, ull a, ull b) {
    asm("fma.rn.f32x2 %0, %1, %2, %0;" : "+l"(acc) : "l"(a), "l"(b));
}
__device__ __forceinline__ ull pack2(float x, float y) {
    ull r; asm("mov.b64 %0, {%1, %2};" : "=l"(r) : "f"(x), "f"(y)); return r;
}
__device__ __forceinline__ float2 unpack2(ull v) {
    float2 r; asm("mov.b64 {%0, %1}, %2;" : "=f"(r.x), "=f"(r.y) : "l"(v)); return r;
}

__device__ __forceinline__ float sigmoidf_fast(float x) {
    return __fdividef(1.0f, 1.0f + __expf(-x));          // EX2 + RCP, rel err ~1e-6
}
__device__ __forceinline__ float tanhf_fast(float x) {
    // 1 - 2/(1+e^{2x}) : correct limits at +/-inf (e->inf => 1, e->0 => -1)
    float e = __expf(2.0f * x);
    return 1.0f - __fdividef(2.0f, e + 1.0f);
}

// ---------------- prep kernel: reorganize weights, fuse fc1+fc2 ----------------
__global__ void prep_kernel(const float* __restrict__ Wih, const float* __restrict__ Whh,
                            const float* __restrict__ bih, const float* __restrict__ bhh,
                            const float* __restrict__ W1,  const float* __restrict__ b1,
                            const float* __restrict__ W2,  const float* __restrict__ b2) {
    int tid = threadIdx.x;
    for (int idx = tid; idx < ROWS * HID; idx += blockDim.x) {
        int row = idx / HID, j = idx % HID;
        int gate = row >> 5, u = row & 31;
        float w = (u < HID) ? Whh[(gate * HID + u) * HID + j] : 0.0f;
        g_Wd[row][j] = make_float2(w, w);
    }
    for (int idx = tid; idx < ROWS * INP; idx += blockDim.x) {
        int row = idx / INP, i = idx % INP;
        int gate = row >> 5, u = row & 31;
        float w = (u < HID) ? Wih[(gate * HID + u) * INP + i] : 0.0f;
        g_Wih[row][i] = make_float2(w, w);
    }
    for (int row = tid; row < ROWS; row += blockDim.x) {
        int gate = row >> 5, u = row & 31;
        g_bias[row] = (u < HID) ? (bih[gate * HID + u] + bhh[gate * HID + u]) : 0.0f;
    }
    for (int idx = tid; idx < HID * OUTD; idx += blockDim.x) {
        int j = idx / OUTD, o = idx % OUTD;
        float s = 0.0f;
        for (int k = 0; k < HID; k++) s += W1[k * HID + j] * W2[o * HID + k];
        g_M[j][o] = s;
    }
    for (int o = tid; o < OUTD; o += blockDim.x) {
        float s = b2[o];
        for (int k = 0; k < HID; k++) s += b1[k] * W2[o * HID + k];
        g_bv[o] = s;
    }
}

// ---------------- X tile stager: transpose [b][i] -> shared [i][b] ----------------
__device__ __forceinline__ void stage_x(const float* __restrict__ X, int t, int bbase,
                                        int tid, float* __restrict__ xbuf /* [INP][BBLK] */) {
    if (tid < (BBLK * INP / 4)) {  // 48 threads, float4 each (region is 16B-aligned)
        const float* p = X + ((size_t)t * BATCH + bbase) * INP;
        float4 v = *(const float4*)(p + tid * 4);
        int lin = tid * 4;
        float vv[4] = {v.x, v.y, v.z, v.w};
#pragma unroll
        for (int m = 0; m < 4; m++) {
            int e = lin + m;
            int b = e / INP, i = e % INP;
            xbuf[i * BBLK + b] = vv[m];
        }
    }
}

// ---------------- main persistent LSTM kernel ----------------
__global__ void __launch_bounds__(NTHR, 1)
lstm_kernel(const float* __restrict__ X, float* __restrict__ out) {
    __shared__ __align__(16) float2 sWd[ROWS][HID];      // 30720 B
    __shared__ __align__(16) float2 sWih[ROWS][INP];     //  6144 B
    __shared__ __align__(16) float  sh[2][HP][BBLK];     //  8192 B (h double buffer, [j][b])
    __shared__ __align__(16) float  sx[2][INP][BBLK];    //  1536 B (x double buffer, [i][b])

    const int tid   = threadIdx.x;
    const int bp    = tid & 15;        // batch-pair id: batches (2bp, 2bp+1)
    const int grp   = tid >> 4;        // unit group: units (2grp, 2grp+1)
    const int bbase = blockIdx.x * BBLK;

    // cooperative weight load to shared
    {
        const float4* s1 = (const float4*)&g_Wd[0][0];
        float4*       d1 = (float4*)&sWd[0][0];
        for (int i = tid; i < ROWS * HID / 2; i += NTHR) d1[i] = s1[i];
        const float4* s2 = (const float4*)&g_Wih[0][0];
        float4*       d2 = (float4*)&sWih[0][0];
        for (int i = tid; i < ROWS * INP / 2; i += NTHR) d2[i] = s2[i];
    }
    // zero h buffer 0
    for (int i = tid; i < HP * BBLK; i += NTHR) (&sh[0][0][0])[i] = 0.0f;
    // stage x for t=0
    stage_x(X, 0, bbase, tid, &sx[0][0][0]);

    // per-thread gate rows (4 gates x 2 units) and packed biases
    const int u0 = 2 * grp;
    int rows[8];
    ull bias2[8];
#pragma unroll
    for (int k = 0; k < 8; k++) {
        int u = u0 + (k >> 2);
        rows[k] = (k & 3) * HP + u;
        float b = g_bias[rows[k]];
        bias2[k] = pack2(b, b);
    }

    ull c2[2];  // cell state for 2 units (each packed over batch pair)
    c2[0] = 0ull; c2[1] = 0ull;

    __syncthreads();

    int cur = 0;
#pragma unroll 1
    for (int t = 0; t < SEQ; ++t) {
        ull acc[8];
#pragma unroll
        for (int k = 0; k < 8; k++) acc[k] = bias2[k];

        const float* hc = &sh[cur][0][0];
        const float* xc = &sx[t & 1][0][0];

        // input projection: 3 i-pairs
#pragma unroll
        for (int i = 0; i < INP; i += 2) {
            ull x0 = *(const ull*)(xc + i * BBLK + 2 * bp);
            ull x1 = *(const ull*)(xc + (i + 1) * BBLK + 2 * bp);
#pragma unroll
            for (int k = 0; k < 8; k++) {
                ulonglong2 w = *(const ulonglong2*)&sWih[rows[k]][i];
                ffma2(acc[k], w.x, x0);
                ffma2(acc[k], w.y, x1);
            }
        }

        // prefetch next step's X tile (other buffer; step-end barrier publishes it)
        if (t + 1 < SEQ) stage_x(X, t + 1, bbase, tid, &sx[(t + 1) & 1][0][0]);

        // recurrent projection: 15 j-pairs
#pragma unroll
        for (int j = 0; j < HID; j += 2) {
            ull h0 = *(const ull*)(hc + j * BBLK + 2 * bp);
            ull h1 = *(const ull*)(hc + (j + 1) * BBLK + 2 * bp);
#pragma unroll
            for (int k = 0; k < 8; k++) {
                ulonglong2 w = *(const ulonglong2*)&sWd[rows[k]][j];
                ffma2(acc[k], w.x, h0);
                ffma2(acc[k], w.y, h1);
            }
        }

        // gate activations + state update (scalar fp32, packed over batch pair)
        float* hn = &sh[cur ^ 1][0][0];
#pragma unroll
        for (int uu = 0; uu < 2; uu++) {
            float2 gi = unpack2(acc[uu * 4 + 0]);
            float2 gf = unpack2(acc[uu * 4 + 1]);
            float2 gg = unpack2(acc[uu * 4 + 2]);
            float2 go = unpack2(acc[uu * 4 + 3]);
            float2 c  = unpack2(c2[uu]);
            float ix = sigmoidf_fast(gi.x), iy = sigmoidf_fast(gi.y);
            float fx = sigmoidf_fast(gf.x), fy = sigmoidf_fast(gf.y);
            float gx = tanhf_fast(gg.x),    gy = tanhf_fast(gg.y);
            float ox = sigmoidf_fast(go.x), oy = sigmoidf_fast(go.y);
            c.x = fx * c.x + ix * gx;
            c.y = fy * c.y + iy * gy;
            c2[uu] = pack2(c.x, c.y);
            float hx = ox * tanhf_fast(c.x);
            float hy = oy * tanhf_fast(c.y);
            *(ull*)(hn + (u0 + uu) * BBLK + 2 * bp) = pack2(hx, hy);
        }

        __syncthreads();
        cur ^= 1;
    }

    // fused fc1+fc2 epilogue: out[b][o] = bv[o] + sum_j h[j][b] * M[j][o]
    const float* hf = &sh[cur][0][0];
    for (int idx = tid; idx < BBLK * OUTD; idx += NTHR) {
        int b = idx / OUTD, o = idx % OUTD;
        float s = g_bv[o];
#pragma unroll
        for (int j = 0; j < HID; j++) s += hf[j * BBLK + b] * g_M[j][o];
        out[(size_t)(bbase + b) * OUTD + o] = s;
    }
}

// ---------------- launch ----------------
extern "C" void kernel_launch(void* const* d_in, const int* in_sizes, int n_in,
                              void* d_out, int out_size) {
    const float* X   = (const float*)d_in[0];
    const float* Wih = (const float*)d_in[1];
    const float* Whh = (const float*)d_in[2];
    const float* bih = (const float*)d_in[3];
    const float* bhh = (const float*)d_in[4];
    const float* W1  = (const float*)d_in[5];
    const float* b1  = (const float*)d_in[6];
    const float* W2  = (const float*)d_in[7];
    const float* b2  = (const float*)d_in[8];

    prep_kernel<<<1, 256>>>(Wih, Whh, bih, bhh, W1, b1, W2, b2);
    lstm_kernel<<<NBLK, NTHR>>>(X, (float*)d_out);
}

// round 2
// speedup vs baseline: 1.0707x; 1.0707x over previous
#include <cuda_runtime.h>

#define SEQ   600
#define BATCH 4096
#define INP   6
#define HID   30
#define OUTD  61
#define UPAD  32            // padded units (threads cover 32 units, 30 real)
#define VLEN  36            // fused state vector: 6 x + 30 h
#define NQ    9             // 36 / 4 quads
#define SVS   44            // v row stride in floats (bank-spread: 44*4B, 16B-aligned)
#define WROW  40            // weight row stride in floats (160B, 16B-aligned)
#define BBLK  32            // batch rows per block
#define NBLK  (BATCH / BBLK)  // 128
#define NTHR  512           // 32 units x 16 batch-groups

typedef unsigned long long ull;

// ---------------- preprocessed weights (device globals) ----------------
__device__ __align__(16) float g_W[4][UPAD][WROW];  // [gate][unit][ Wih(6) | Whh(30) | 0pad ]
__device__ float g_bias[4][UPAD];                   // b_ih + b_hh (0 for pad units)
__device__ float g_M[HID][OUTD];                    // fused fc1+fc2: M[j][o]
__device__ float g_bv[OUTD];                        // b2 + b1 @ W2^T

// ---------------- packed f32x2 helpers ----------------
__device__ __forceinline__ void ffma2(ull& acc, ull a, ull b) {
    asm("fma.rn.f32x2 %0, %1, %2, %0;" : "+l"(acc) : "l"(a), "l"(b));
}
__device__ __forceinline__ ull pack2(float x, float y) {
    ull r; asm("mov.b64 %0, {%1, %2};" : "=l"(r) : "f"(x), "f"(y)); return r;
}
__device__ __forceinline__ float hsum2(ull v) {
    float2 r; asm("mov.b64 {%0, %1}, %2;" : "=f"(r.x), "=f"(r.y) : "l"(v));
    return r.x + r.y;
}
__device__ __forceinline__ float sigmoidf_fast(float x) {
    return __fdividef(1.0f, 1.0f + __expf(-x));
}
__device__ __forceinline__ float tanhf_fast(float x) {
    float e = __expf(2.0f * x);
    return 1.0f - __fdividef(2.0f, e + 1.0f);
}

// ---------------- prep kernel ----------------
__global__ void prep_kernel(const float* __restrict__ Wih, const float* __restrict__ Whh,
                            const float* __restrict__ bih, const float* __restrict__ bhh,
                            const float* __restrict__ W1,  const float* __restrict__ b1,
                            const float* __restrict__ W2,  const float* __restrict__ b2) {
    int tid = threadIdx.x;
    for (int idx = tid; idx < 4 * UPAD * WROW; idx += blockDim.x) {
        int g = idx / (UPAD * WROW);
        int r = idx % (UPAD * WROW);
        int u = r / WROW, j = r % WROW;
        float w = 0.0f;
        if (u < HID) {
            if (j < INP)       w = Wih[(g * HID + u) * INP + j];
            else if (j < VLEN) w = Whh[(g * HID + u) * HID + (j - INP)];
        }
        g_W[g][u][j] = w;
    }
    for (int idx = tid; idx < 4 * UPAD; idx += blockDim.x) {
        int g = idx / UPAD, u = idx % UPAD;
        g_bias[g][u] = (u < HID) ? (bih[g * HID + u] + bhh[g * HID + u]) : 0.0f;
    }
    for (int idx = tid; idx < HID * OUTD; idx += blockDim.x) {
        int j = idx / OUTD, o = idx % OUTD;
        float s = 0.0f;
        for (int k = 0; k < HID; k++) s += W1[k * HID + j] * W2[o * HID + k];
        g_M[j][o] = s;
    }
    for (int o = tid; o < OUTD; o += blockDim.x) {
        float s = b2[o];
        for (int k = 0; k < HID; k++) s += b1[k] * W2[o * HID + k];
        g_bv[o] = s;
    }
}

// ---------------- X tile stager: [b][i] gmem -> v-buffer x-section ----------------
__device__ __forceinline__ void stage_x(const float* __restrict__ X, int t, int bbase,
                                        int tid, float* __restrict__ vbuf /* [BBLK][SVS] */) {
    if (tid < (BBLK * INP / 4)) {  // 48 threads x float4 (region 16B aligned: bbase*6*4 = 768B)
        const float* p = X + ((size_t)t * BATCH + bbase) * INP;
        float4 v = *(const float4*)(p + tid * 4);
        int lin = tid * 4;
        float vv[4] = {v.x, v.y, v.z, v.w};
#pragma unroll
        for (int m = 0; m < 4; m++) {
            int e = lin + m;
            int b = e / INP, i = e % INP;
            vbuf[b * SVS + i] = vv[m];
        }
    }
}

// ---------------- main persistent LSTM kernel ----------------
__global__ void __launch_bounds__(NTHR, 1)
lstm_kernel(const float* __restrict__ X, float* __restrict__ out) {
    __shared__ __align__(16) float sW[4][UPAD][WROW];   // 20480 B
    __shared__ __align__(16) float sv[2][BBLK][SVS];    // 11264 B, v = [x|h] double buffer

    const int tid   = threadIdx.x;
    const int bg    = tid & 15;         // batch group -> batches (bg, bg+16)
    const int u     = tid >> 4;         // unit 0..31 (30 real, 2 pad)
    const int bbase = blockIdx.x * BBLK;

    // cooperative weight load to shared
    {
        const float4* s = (const float4*)&g_W[0][0][0];
        float4*       d = (float4*)&sW[0][0][0];
        for (int i = tid; i < 4 * UPAD * WROW / 4; i += NTHR) d[i] = s[i];
    }
    // zero v buffers (h section must be 0 for t=0; pads stay benign)
    for (int i = tid; i < 2 * BBLK * SVS; i += NTHR) (&sv[0][0][0])[i] = 0.0f;
    // stage x for t=0
    stage_x(X, 0, bbase, tid, &sv[0][0][0]);

    // per-thread packed biases: acc layout acc[2*gate + pb], init {bias, 0}
    ull bias2[4];
#pragma unroll
    for (int g = 0; g < 4; g++) bias2[g] = pack2(g_bias[g][u], 0.0f);

    float c0 = 0.0f, c1 = 0.0f;   // cell state for (u, bg) and (u, bg+16)

    __syncthreads();

    int cur = 0;
#pragma unroll 1
    for (int t = 0; t < SEQ; ++t) {
        // prefetch next step's X into the other buffer (x-section only; published by barrier)
        if (t + 1 < SEQ) stage_x(X, t + 1, bbase, tid, &sv[cur ^ 1][0][0]);

        const float* vb0 = &sv[cur][bg][0];
        const float* vb1 = &sv[cur][bg + 16][0];

        ull acc[8];
#pragma unroll
        for (int g = 0; g < 4; g++) { acc[2 * g] = bias2[g]; acc[2 * g + 1] = bias2[g]; }

        // fused input+recurrent projection: 9 j-quads over v = [x(6)|h(30)]
#pragma unroll
        for (int q = 0; q < NQ; ++q) {
            ulonglong2 V0 = *(const ulonglong2*)(vb0 + 4 * q);   // {v_j,v_j+1},{v_j+2,v_j+3}
            ulonglong2 V1 = *(const ulonglong2*)(vb1 + 4 * q);
#pragma unroll
            for (int g = 0; g < 4; ++g) {
                ulonglong2 W = *(const ulonglong2*)(&sW[g][u][4 * q]);
                ffma2(acc[2 * g],     W.x, V0.x);
                ffma2(acc[2 * g],     W.y, V0.y);
                ffma2(acc[2 * g + 1], W.x, V1.x);
                ffma2(acc[2 * g + 1], W.y, V1.y);
            }
        }

        // gate activations + state update; write h into next buffer's h-section
        float* hn = &sv[cur ^ 1][0][0];
        {
            float i_ = sigmoidf_fast(hsum2(acc[0]));
            float f_ = sigmoidf_fast(hsum2(acc[2]));
            float g_ = tanhf_fast   (hsum2(acc[4]));
            float o_ = sigmoidf_fast(hsum2(acc[6]));
            c0 = f_ * c0 + i_ * g_;
            hn[bg * SVS + INP + u] = o_ * tanhf_fast(c0);
        }
        {
            float i_ = sigmoidf_fast(hsum2(acc[1]));
            float f_ = sigmoidf_fast(hsum2(acc[3]));
            float g_ = tanhf_fast   (hsum2(acc[5]));
            float o_ = sigmoidf_fast(hsum2(acc[7]));
            c1 = f_ * c1 + i_ * g_;
            hn[(bg + 16) * SVS + INP + u] = o_ * tanhf_fast(c1);
        }

        __syncthreads();
        cur ^= 1;
    }

    // fused fc1+fc2 epilogue: out[b][o] = bv[o] + sum_j h[j] * M[j][o]
    const float* hf = &sv[cur][0][0];
    for (int idx = tid; idx < BBLK * OUTD; idx += NTHR) {
        int b = idx / OUTD, o = idx % OUTD;
        float s = g_bv[o];
#pragma unroll
        for (int j = 0; j < HID; j++) s += hf[b * SVS + INP + j] * g_M[j][o];
        out[(size_t)(bbase + b) * OUTD + o] = s;
    }
}

// ---------------- launch ----------------
extern "C" void kernel_launch(void* const* d_in, const int* in_sizes, int n_in,
                              void* d_out, int out_size) {
    const float* X   = (const float*)d_in[0];
    const float* Wih = (const float*)d_in[1];
    const float* Whh = (const float*)d_in[2];
    const float* bih = (const float*)d_in[3];
    const float* bhh = (const float*)d_in[4];
    const float* W1  = (const float*)d_in[5];
    const float* b1  = (const float*)d_in[6];
    const float* W2  = (const float*)d_in[7];
    const float* b2  = (const float*)d_in[8];

    prep_kernel<<<1, 256>>>(Wih, Whh, bih, bhh, W1, b1, W2, b2);
    lstm_kernel<<<NBLK, NTHR>>>(X, (float*)d_out);
}

// round 4
// speedup vs baseline: 1.2357x; 1.1541x over previous
#include <cuda_runtime.h>

#define SEQ   600
#define BATCH 4096
#define INP   6
#define HID   30
#define OUTD  61
#define UPAD  32            // padded units
#define VLEN  36            // fused state vector: 6 x + 30 h
#define NQ    9             // 36 / 4 quads
#define SVS   44            // v row stride in floats (bank-spread, 16B-aligned)
#define WROW  40            // weight row stride in floats (160B, 16B-aligned)
#define BBLK  32            // batch rows per block
#define NBLK  (BATCH / BBLK)  // 128
#define NTHR  512
#define NDOM  4             // independent sync domains per block
#define DOMB  (BBLK / NDOM) // 8 batches per domain
#define DTHR  (NTHR / NDOM) // 128 threads per domain

typedef unsigned long long ull;

// ---------------- preprocessed weights (device globals) ----------------
__device__ __align__(16) float g_W[4][UPAD][WROW];  // [gate][unit][ Wih(6) | Whh(30) | 0pad ]
__device__ float g_bias[4][UPAD];                   // b_ih + b_hh (0 for pad units)
__device__ float g_M[HID][OUTD];                    // fused fc1+fc2: M[j][o]
__device__ float g_bv[OUTD];                        // b2 + b1 @ W2^T

// ---------------- packed f32x2 + activation helpers ----------------
__device__ __forceinline__ void ffma2(ull& acc, ull a, ull b) {
    asm("fma.rn.f32x2 %0, %1, %2, %0;" : "+l"(acc) : "l"(a), "l"(b));
}
__device__ __forceinline__ ull pack2(float x, float y) {
    ull r; asm("mov.b64 %0, {%1, %2};" : "=l"(r) : "f"(x), "f"(y)); return r;
}
__device__ __forceinline__ float hsum2(ull v) {
    float2 r; asm("mov.b64 {%0, %1}, %2;" : "=f"(r.x), "=f"(r.y) : "l"(v));
    return r.x + r.y;
}
__device__ __forceinline__ float tanh_fast(float x) {
    float r; asm("tanh.approx.f32 %0, %1;" : "=f"(r) : "f"(x)); return r;
}
__device__ __forceinline__ float sigmoid_fast(float x) {
    return fmaf(0.5f, tanh_fast(0.5f * x), 0.5f);
}

// ---------------- prep kernel ----------------
__global__ void prep_kernel(const float* __restrict__ Wih, const float* __restrict__ Whh,
                            const float* __restrict__ bih, const float* __restrict__ bhh,
                            const float* __restrict__ W1,  const float* __restrict__ b1,
                            const float* __restrict__ W2,  const float* __restrict__ b2) {
    int tid = threadIdx.x;
    for (int idx = tid; idx < 4 * UPAD * WROW; idx += blockDim.x) {
        int g = idx / (UPAD * WROW);
        int r = idx % (UPAD * WROW);
        int u = r / WROW, j = r % WROW;
        float w = 0.0f;
        if (u < HID) {
            if (j < INP)       w = Wih[(g * HID + u) * INP + j];
            else if (j < VLEN) w = Whh[(g * HID + u) * HID + (j - INP)];
        }
        g_W[g][u][j] = w;
    }
    for (int idx = tid; idx < 4 * UPAD; idx += blockDim.x) {
        int g = idx / UPAD, u = idx % UPAD;
        g_bias[g][u] = (u < HID) ? (bih[g * HID + u] + bhh[g * HID + u]) : 0.0f;
    }
    for (int idx = tid; idx < HID * OUTD; idx += blockDim.x) {
        int j = idx / OUTD, o = idx % OUTD;
        float s = 0.0f;
        for (int k = 0; k < HID; k++) s += W1[k * HID + j] * W2[o * HID + k];
        g_M[j][o] = s;
    }
    for (int o = tid; o < OUTD; o += blockDim.x) {
        float s = b2[o];
        for (int k = 0; k < HID; k++) s += b1[k] * W2[o * HID + k];
        g_bv[o] = s;
    }
}

// ---------------- per-domain X stager: 8 batches, 12 float4 loads ----------------
__device__ __forceinline__ void stage_x(const float* __restrict__ X, int t, int bfirst,
                                        int lt, float* __restrict__ vbuf /* [BBLK][SVS] base */,
                                        int domb0 /* first batch row of domain in sv */) {
    if (lt < (DOMB * INP / 4)) {  // 12 threads x float4; (bfirst*6*4B) = 192B-aligned
        const float* p = X + ((size_t)t * BATCH + bfirst) * INP;
        float4 v = *(const float4*)(p + lt * 4);
        int lin = lt * 4;
        float vv[4] = {v.x, v.y, v.z, v.w};
#pragma unroll
        for (int m = 0; m < 4; m++) {
            int e = lin + m;
            int b = e / INP, i = e % INP;
            vbuf[(domb0 + b) * SVS + i] = vv[m];
        }
    }
}

// ---------------- main persistent LSTM kernel ----------------
__global__ void __launch_bounds__(NTHR, 1)
lstm_kernel(const float* __restrict__ X, float* __restrict__ out) {
    __shared__ __align__(16) float sW[4][UPAD][WROW];   // 20480 B (shared by all domains)
    __shared__ __align__(16) float sv[2][BBLK][SVS];    // 11264 B, v = [x|h] double buffer

    const int tid   = threadIdx.x;
    const int dom   = tid >> 7;          // sync domain 0..3 (warps 4d..4d+3)
    const int lt    = tid & (DTHR - 1);  // 0..127 within domain
    const int bg    = lt & 3;            // batch group within domain
    const int u     = lt >> 2;           // unit 0..31 (30 real, 2 pad)
    const int bbase = blockIdx.x * BBLK;
    const int domb0 = dom * DOMB;        // domain's first batch row in sv
    const int b0    = domb0 + bg;        // this thread's batch rows in sv
    const int b1    = b0 + 4;
    const int barid = 1 + dom;

    // cooperative weight load to shared (whole block)
    {
        const float4* s = (const float4*)&g_W[0][0][0];
        float4*       d = (float4*)&sW[0][0][0];
        for (int i = tid; i < 4 * UPAD * WROW / 4; i += NTHR) d[i] = s[i];
    }
    // zero v buffers (h must start at 0)
    for (int i = tid; i < 2 * BBLK * SVS; i += NTHR) (&sv[0][0][0])[i] = 0.0f;
    // stage x for t=0 (per domain)
    stage_x(X, 0, bbase + domb0, lt, &sv[0][0][0], domb0);

    // packed biases {bias, 0}; hsum adds halves so init one lane only
    ull bias2[4];
#pragma unroll
    for (int g = 0; g < 4; g++) bias2[g] = pack2(g_bias[g][u], 0.0f);

    float c0 = 0.0f, c1 = 0.0f;

    __syncthreads();   // publishes weights + zeroed sv to all domains

    int cur = 0;
#pragma unroll 1
    for (int t = 0; t < SEQ; ++t) {
        // prefetch next step's X into the other buffer (published by domain barrier)
        if (t + 1 < SEQ) stage_x(X, t + 1, bbase + domb0, lt, &sv[cur ^ 1][0][0], domb0);

        const float* vb0 = &sv[cur][b0][0];
        const float* vb1 = &sv[cur][b1][0];

        ull acc[8];
#pragma unroll
        for (int g = 0; g < 4; g++) { acc[2 * g] = bias2[g]; acc[2 * g + 1] = bias2[g]; }

        // fused input+recurrent projection: 9 j-quads over v = [x(6)|h(30)]
#pragma unroll
        for (int q = 0; q < NQ; ++q) {
            ulonglong2 V0 = *(const ulonglong2*)(vb0 + 4 * q);
            ulonglong2 V1 = *(const ulonglong2*)(vb1 + 4 * q);
#pragma unroll
            for (int g = 0; g < 4; ++g) {
                ulonglong2 W = *(const ulonglong2*)(&sW[g][u][4 * q]);
                ffma2(acc[2 * g],     W.x, V0.x);
                ffma2(acc[2 * g],     W.y, V0.y);
                ffma2(acc[2 * g + 1], W.x, V1.x);
                ffma2(acc[2 * g + 1], W.y, V1.y);
            }
        }

        // gate activations + state update (HW tanh); write h into next buffer
        float* hn = &sv[cur ^ 1][0][0];
        {
            float i_ = sigmoid_fast(hsum2(acc[0]));
            float f_ = sigmoid_fast(hsum2(acc[2]));
            float g_ = tanh_fast   (hsum2(acc[4]));
            float o_ = sigmoid_fast(hsum2(acc[6]));
            c0 = f_ * c0 + i_ * g_;
            hn[b0 * SVS + INP + u] = o_ * tanh_fast(c0);
        }
        {
            float i_ = sigmoid_fast(hsum2(acc[1]));
            float f_ = sigmoid_fast(hsum2(acc[3]));
            float g_ = tanh_fast   (hsum2(acc[5]));
            float o_ = sigmoid_fast(hsum2(acc[7]));
            c1 = f_ * c1 + i_ * g_;
            hn[b1 * SVS + INP + u] = o_ * tanh_fast(c1);
        }

        // domain-local barrier: only this domain's 128 threads sync
        asm volatile("bar.sync %0, %1;" :: "r"(barid), "n"(DTHR) : "memory");
        cur ^= 1;
    }

    // fused fc1+fc2 epilogue, per domain: out[b][o] = bv[o] + sum_j h[j]*M[j][o]
    const float* hf = &sv[cur][0][0];
    for (int idx = lt; idx < DOMB * OUTD; idx += DTHR) {
        int b = idx / OUTD, o = idx % OUTD;
        float s = g_bv[o];
#pragma unroll
        for (int j = 0; j < HID; j++) s += hf[(domb0 + b) * SVS + INP + j] * g_M[j][o];
        out[(size_t)(bbase + domb0 + b) * OUTD + o] = s;
    }
}

// ---------------- launch ----------------
extern "C" void kernel_launch(void* const* d_in, const int* in_sizes, int n_in,
                              void* d_out, int out_size) {
    const float* X   = (const float*)d_in[0];
    const float* Wih = (const float*)d_in[1];
    const float* Whh = (const float*)d_in[2];
    const float* bih = (const float*)d_in[3];
    const float* bhh = (const float*)d_in[4];
    const float* W1  = (const float*)d_in[5];
    const float* b1  = (const float*)d_in[6];
    const float* W2  = (const float*)d_in[7];
    const float* b2  = (const float*)d_in[8];

    prep_kernel<<<1, 256>>>(Wih, Whh, bih, bhh, W1, b1, W2, b2);
    lstm_kernel<<<NBLK, NTHR>>>(X, (float*)d_out);
}